// round 15
// baseline (speedup 1.0000x reference)
#include <cuda_runtime.h>
#include <cuda_fp16.h>
#include <math.h>
#include <stdint.h>

#define HD   1024
#define SEQ  1024
#define LO   256
#define LDOC 768
#define NBAT 32
#define NBZ  8
#define NL   4

// ---------------- fp32 scratch ----------------
__device__ float g_S [96 * LO * LO];
__device__ float g_kl[NBAT * LDOC];
__device__ float g_ql[NBAT * LO];

// ---------------- fp16 buffers ----------------
__device__ __half h_last [NBAT * SEQ * HD];
__device__ __half h_mul  [96 * LO * HD];
__device__ __half h_sub  [96 * LO * HD];
__device__ __half h_P    [96 * LO * LO];
__device__ __half h_kq   [NBAT * LO * LDOC];
__device__ __half h_cow  [NBAT * LO * LO];
__device__ __half h_corr [NBAT * LO * HD];
__device__ __half h_opt  [NBAT * LO * HD];
__device__ __half h_a    [NBAT * LO * HD];
__device__ __half h_co   [NBAT * LO * HD];
__device__ __half h_fus  [NBAT * LO * HD];
__device__ __half h_sa   [NBAT * LO * HD];
__device__ __half h_fm   [NBAT * LO * HD];
__device__ __half h_fs   [NBAT * LO * HD];
__device__ __half h_compw[7 * HD * HD];
__device__ __half h_gatew[2 * HD * HD];
__device__ __half h_attnw[3 * HD * HD];
__device__ __half h_selfw[4 * HD * HD];
__device__ __half h_aff  [4 * HD];   // [ow3 | ow2 | sw3 | sw2]

struct ZOffs { long long o[12]; };
struct HSeg  { const __half* A; long long c0, c1, s0; };
struct HSegArgs { HSeg segs[8]; int nseg; };

// ---------------- helpers ----------------
__device__ __forceinline__ void cpa16(uint32_t dst, const void* src) {
    asm volatile("cp.async.cg.shared.global [%0], [%1], 16;" :: "r"(dst), "l"(src));
}
#define CP_COMMIT() asm volatile("cp.async.commit_group;" ::: "memory")
#define CP_WAIT2()  asm volatile("cp.async.wait_group 2;" ::: "memory")

__device__ __forceinline__ unsigned hscale2u(unsigned a, __half2 s) {
    __half2 x = __hmul2(*reinterpret_cast<__half2*>(&a), s);
    return *reinterpret_cast<unsigned*>(&x);
}
__device__ __forceinline__ unsigned hfma2u(unsigned a, __half2 s, __half2 o) {
    __half2 x = __hfma2(*reinterpret_cast<__half2*>(&a), s, o);
    return *reinterpret_cast<unsigned*>(&x);
}

__device__ __forceinline__ void ldsm_x4(unsigned& r0, unsigned& r1, unsigned& r2, unsigned& r3,
                                        uint32_t addr) {
    asm volatile("ldmatrix.sync.aligned.m8n8.x4.shared.b16 {%0,%1,%2,%3}, [%4];"
                 : "=r"(r0), "=r"(r1), "=r"(r2), "=r"(r3) : "r"(addr));
}
__device__ __forceinline__ void ldsm_x4_trans(unsigned& r0, unsigned& r1, unsigned& r2, unsigned& r3,
                                              uint32_t addr) {
    asm volatile("ldmatrix.sync.aligned.m8n8.x4.trans.shared.b16 {%0,%1,%2,%3}, [%4];"
                 : "=r"(r0), "=r"(r1), "=r"(r2), "=r"(r3) : "r"(addr));
}

__device__ __forceinline__ float blockReduceMax(float v, float* sm) {
    #pragma unroll
    for (int o = 16; o; o >>= 1) v = fmaxf(v, __shfl_xor_sync(0xffffffffu, v, o));
    int w = threadIdx.x >> 5;
    if ((threadIdx.x & 31) == 0) sm[w] = v;
    __syncthreads();
    if (threadIdx.x < 32) {
        v = (threadIdx.x < (blockDim.x >> 5)) ? sm[threadIdx.x] : -3.4e38f;
        #pragma unroll
        for (int o = 4; o; o >>= 1) v = fmaxf(v, __shfl_xor_sync(0xffffffffu, v, o));
        if (threadIdx.x == 0) sm[0] = v;
    }
    __syncthreads();
    v = sm[0];
    __syncthreads();
    return v;
}

__device__ __forceinline__ float blockReduceSum(float v, float* sm) {
    #pragma unroll
    for (int o = 16; o; o >>= 1) v += __shfl_xor_sync(0xffffffffu, v, o);
    int w = threadIdx.x >> 5;
    if ((threadIdx.x & 31) == 0) sm[w] = v;
    __syncthreads();
    if (threadIdx.x < 32) {
        v = (threadIdx.x < (blockDim.x >> 5)) ? sm[threadIdx.x] : 0.0f;
        #pragma unroll
        for (int o = 4; o; o >>= 1) v += __shfl_xor_sync(0xffffffffu, v, o);
        if (threadIdx.x == 0) sm[0] = v;
    }
    __syncthreads();
    v = sm[0];
    __syncthreads();
    return v;
}

#define BM 128
#define BN 128
#define ASTR 20
#define STG 2560
#define BOFF 10240
#define BNNP 68
#define NNSTG 2176
#define NT_SMEM 81920
#define NN_SMEM 75776

// A fragments via ldmatrix.x4: per-lane address components
#define A_LANE_ROW ((lane & 7) + ((lane >> 3) & 1) * 8)
#define A_LANE_COL (((lane >> 4) & 1) * 4)

#define NT16_MMA()                                                                   \
    _Pragma("unroll")                                                                \
    for (int mt = 0; mt < 4; ++mt)                                                   \
        _Pragma("unroll")                                                            \
        for (int nt = 0; nt < 4; ++nt) {                                             \
            asm volatile(                                                            \
                "mma.sync.aligned.m16n8k16.row.col.f32.f16.f16.f32 "                 \
                "{%0,%1,%2,%3}, {%4,%5,%6,%7}, {%8,%9}, {%0,%1,%2,%3};"              \
                : "+f"(cfr[mt][nt][0]), "+f"(cfr[mt][nt][1]),                        \
                  "+f"(cfr[mt][nt][2]), "+f"(cfr[mt][nt][3])                         \
                : "r"(af[mt][0]), "r"(af[mt][1]), "r"(af[mt][2]), "r"(af[mt][3]),    \
                  "r"(bf[nt][0]), "r"(bf[nt][1]));                                   \
        }

// ================= fp16 NT GEMM (cp.async 4-stage, ldmatrix frags) =================
// AFF=1: A-fragment affine a' = s*a + o (fp16 vectors over k). BSC: fp32 B k-scale.
template <int OUT16, int AFF>
__global__ __launch_bounds__(256)
void tgemm_kernel(int K,
                  const __half* __restrict__ A, int lda, long long sA0, ZOffs aoffs,
                  const __half* __restrict__ B, int ldb, long long sB0, ZOffs boffs,
                  void* __restrict__ Cv, int ldc, long long sC0, ZOffs coffs,
                  int nz0, const float* __restrict__ bscale,
                  const __half* __restrict__ aff_s, const __half* __restrict__ aff_o)
{
    extern __shared__ unsigned dsm[];
    const uint32_t sb = (uint32_t)__cvta_generic_to_shared(dsm);

    const int z  = blockIdx.z;
    const int z1 = z / nz0;
    const int z0 = z - z1 * nz0;
    const __half* Ab = A + aoffs.o[z1] + (long long)z0 * sA0;
    const __half* Bb = B + boffs.o[z1] + (long long)z0 * sB0;

    const int bm = blockIdx.y * BM;
    const int bn = blockIdx.x * BN;
    const int tid  = threadIdx.x;
    const int lane = tid & 31;
    const int warp = tid >> 5;
    const int warpM = warp >> 2;
    const int warpN = warp & 3;
    const int g = lane >> 2;
    const int c = lane & 3;

    const int lrow  = tid >> 1;
    const int lpart = tid & 1;
    const int aRow = A_LANE_ROW, aCol = A_LANE_COL;
    const int bRowOff = (2 * 0 + (lane >> 4)) * 8 + (lane & 7);  // + ntp*16
    const int bCol = ((lane >> 3) & 1) * 4;

    const __half2* hs = AFF ? reinterpret_cast<const __half2*>(aff_s) : nullptr;
    const __half2* ho = AFF ? reinterpret_cast<const __half2*>(aff_o) : nullptr;

    float cfr[4][4][4];
    #pragma unroll
    for (int mt = 0; mt < 4; ++mt)
        #pragma unroll
        for (int nt = 0; nt < 4; ++nt)
            #pragma unroll
            for (int r = 0; r < 4; ++r) cfr[mt][nt][r] = 0.0f;

    auto issue = [&](int s, int k0) {
        uint32_t ad = sb + (uint32_t)((s * STG + lrow * ASTR + lpart * 8) * 4);
        const __half* ap = Ab + (long long)(bm + lrow) * lda + k0 + lpart * 16;
        cpa16(ad, ap); cpa16(ad + 16, ap + 8);
        uint32_t bd = sb + (uint32_t)(((BOFF + s * STG) + lrow * ASTR + lpart * 8) * 4);
        const __half* bp = Bb + (long long)(bn + lrow) * ldb + k0 + lpart * 16;
        cpa16(bd, bp); cpa16(bd + 16, bp + 8);
    };

    auto compute = [&](int s, int k0) {
        const uint32_t Au = sb + (uint32_t)(s * STG * 4);
        const uint32_t Bu = sb + (uint32_t)((BOFF + s * STG) * 4);
        #pragma unroll
        for (int kk = 0; kk < 2; ++kk) {
            unsigned af[4][4], bf[4][2];
            #pragma unroll
            for (int mt = 0; mt < 4; ++mt) {
                const uint32_t addr = Au +
                    (uint32_t)(((warpM * 64 + mt * 16 + aRow) * ASTR + kk * 8 + aCol) * 4);
                ldsm_x4(af[mt][0], af[mt][1], af[mt][2], af[mt][3], addr);
            }
            #pragma unroll
            for (int ntp = 0; ntp < 2; ++ntp) {
                const uint32_t addr = Bu +
                    (uint32_t)(((warpN * 32 + ntp * 16 + bRowOff) * ASTR + kk * 8 + bCol) * 4);
                ldsm_x4(bf[2 * ntp][0], bf[2 * ntp][1], bf[2 * ntp + 1][0], bf[2 * ntp + 1][1], addr);
            }
            if (AFF) {
                const int kb = (k0 >> 1) + kk * 8 + c;   // half2 index at k = k0+kk*16+2c
                const __half2 s0 = hs[kb],     o0 = ho[kb];
                const __half2 s1 = hs[kb + 4], o1 = ho[kb + 4];
                #pragma unroll
                for (int mt = 0; mt < 4; ++mt) {
                    af[mt][0] = hfma2u(af[mt][0], s0, o0);
                    af[mt][1] = hfma2u(af[mt][1], s0, o0);
                    af[mt][2] = hfma2u(af[mt][2], s1, o1);
                    af[mt][3] = hfma2u(af[mt][3], s1, o1);
                }
            }
            if (bscale) {
                const int kb = k0 + kk * 16 + 2 * c;
                __half2 s0 = __floats2half2_rn(bscale[kb], bscale[kb + 1]);
                __half2 s1 = __floats2half2_rn(bscale[kb + 8], bscale[kb + 9]);
                #pragma unroll
                for (int nt = 0; nt < 4; ++nt) {
                    bf[nt][0] = hscale2u(bf[nt][0], s0);
                    bf[nt][1] = hscale2u(bf[nt][1], s1);
                }
            }
            NT16_MMA()
        }
    };

    const int T = K / 32;
    issue(0, 0);  CP_COMMIT();
    issue(1, 32); CP_COMMIT();
    issue(2, 64); CP_COMMIT();
    for (int t = 0; t < T; ++t) {
        CP_WAIT2();
        __syncthreads();
        compute(t & 3, t * 32);
        if (t + 3 < T) issue((t + 3) & 3, (t + 3) * 32);
        CP_COMMIT();
    }

    #pragma unroll
    for (int mt = 0; mt < 4; ++mt) {
        const int row = bm + warpM * 64 + mt * 16 + g;
        #pragma unroll
        for (int nt = 0; nt < 4; ++nt) {
            const int col = bn + warpN * 32 + nt * 8 + c * 2;
            #pragma unroll
            for (int half = 0; half < 2; ++half) {
                const int r2 = row + half * 8;
                float v0 = cfr[mt][nt][half * 2 + 0];
                float v1 = cfr[mt][nt][half * 2 + 1];
                if (OUT16) {
                    __half* Ch = (__half*)Cv + coffs.o[z1] + (long long)z0 * sC0;
                    *reinterpret_cast<__half2*>(Ch + (long long)r2 * ldc + col) =
                        __floats2half2_rn(v0, v1);
                } else {
                    float* Cf = (float*)Cv + coffs.o[z1] + (long long)z0 * sC0;
                    float* p = Cf + (long long)r2 * ldc + col;
                    p[0] = v0; p[1] = v1;
                }
            }
        }
    }
}

// ================= fp16 segmented-K NT GEMM (cp.async 4-stage, ldmatrix frags) ======
__global__ __launch_bounds__(256)
void segk_kernel(int Ktot, HSegArgs sga,
                 const __half* __restrict__ B, int ldb,
                 __half* __restrict__ C, int ldc, long long sC0, ZOffs coffs, int nz0,
                 const float* __restrict__ bias, int act,
                 const __half* __restrict__ e1, long long e1s,
                 const __half* __restrict__ e2, long long e2s)
{
    extern __shared__ unsigned dsm[];
    const uint32_t sb = (uint32_t)__cvta_generic_to_shared(dsm);

    const int z  = blockIdx.z;
    const int z1 = z / nz0;
    const int z0 = z - z1 * nz0;
    __half* Cb = C + coffs.o[z1] + (long long)z0 * sC0;

    const int bm = blockIdx.y * BM;
    const int bn = blockIdx.x * BN;
    const int tid  = threadIdx.x;
    const int lane = tid & 31;
    const int warp = tid >> 5;
    const int warpM = warp >> 2;
    const int warpN = warp & 3;
    const int g = lane >> 2;
    const int c = lane & 3;

    const int lrow  = tid >> 1;
    const int lpart = tid & 1;
    const int aRow = A_LANE_ROW, aCol = A_LANE_COL;
    const int bRowOff = (lane >> 4) * 8 + (lane & 7);
    const int bCol = ((lane >> 3) & 1) * 4;

    int curseg = -1;
    const __half* Ab = nullptr;

    float cfr[4][4][4];
    #pragma unroll
    for (int mt = 0; mt < 4; ++mt)
        #pragma unroll
        for (int nt = 0; nt < 4; ++nt)
            #pragma unroll
            for (int r = 0; r < 4; ++r) cfr[mt][nt][r] = 0.0f;

    auto issue = [&](int s, int k0) {
        const int sg = k0 >> 10;
        if (sg != curseg) {
            curseg = sg;
            const HSeg& h = sga.segs[sg];
            Ab = h.A + h.c0 + h.c1 * z1 + h.s0 * z0;
        }
        const int kl = k0 & 1023;
        uint32_t ad = sb + (uint32_t)((s * STG + lrow * ASTR + lpart * 8) * 4);
        const __half* ap = Ab + (long long)(bm + lrow) * 1024 + kl + lpart * 16;
        cpa16(ad, ap); cpa16(ad + 16, ap + 8);
        uint32_t bd = sb + (uint32_t)(((BOFF + s * STG) + lrow * ASTR + lpart * 8) * 4);
        const __half* bp = B + (long long)(bn + lrow) * ldb + k0 + lpart * 16;
        cpa16(bd, bp); cpa16(bd + 16, bp + 8);
    };

    auto compute = [&](int s) {
        const uint32_t Au = sb + (uint32_t)(s * STG * 4);
        const uint32_t Bu = sb + (uint32_t)((BOFF + s * STG) * 4);
        #pragma unroll
        for (int kk = 0; kk < 2; ++kk) {
            unsigned af[4][4], bf[4][2];
            #pragma unroll
            for (int mt = 0; mt < 4; ++mt) {
                const uint32_t addr = Au +
                    (uint32_t)(((warpM * 64 + mt * 16 + aRow) * ASTR + kk * 8 + aCol) * 4);
                ldsm_x4(af[mt][0], af[mt][1], af[mt][2], af[mt][3], addr);
            }
            #pragma unroll
            for (int ntp = 0; ntp < 2; ++ntp) {
                const uint32_t addr = Bu +
                    (uint32_t)(((warpN * 32 + ntp * 16 + bRowOff) * ASTR + kk * 8 + bCol) * 4);
                ldsm_x4(bf[2 * ntp][0], bf[2 * ntp][1], bf[2 * ntp + 1][0], bf[2 * ntp + 1][1], addr);
            }
            NT16_MMA()
        }
    };

    const int T = Ktot / 32;
    issue(0, 0);  CP_COMMIT();
    issue(1, 32); CP_COMMIT();
    issue(2, 64); CP_COMMIT();
    for (int t = 0; t < T; ++t) {
        CP_WAIT2();
        __syncthreads();
        compute(t & 3);
        if (t + 3 < T) issue((t + 3) & 3, (t + 3) * 32);
        CP_COMMIT();
    }

    #pragma unroll
    for (int mt = 0; mt < 4; ++mt) {
        const int row = bm + warpM * 64 + mt * 16 + g;
        #pragma unroll
        for (int nt = 0; nt < 4; ++nt) {
            const int col = bn + warpN * 32 + nt * 8 + c * 2;
            #pragma unroll
            for (int half = 0; half < 2; ++half) {
                const int r2 = row + half * 8;
                float v0 = cfr[mt][nt][half * 2 + 0];
                float v1 = cfr[mt][nt][half * 2 + 1];
                if (bias) { v0 += bias[col]; v1 += bias[col + 1]; }
                if (act == 1)      { v0 = fmaxf(v0, 0.0f); v1 = fmaxf(v1, 0.0f); }
                else if (act == 2) { v0 = tanhf(v0); v1 = tanhf(v1); }
                else if (act == 4) {
                    const float g0 = 1.0f / (1.0f + expf(-v0));
                    const float g1 = 1.0f / (1.0f + expf(-v1));
                    const __half* pe = e1 + (long long)z0 * e1s + (long long)r2 * ldc + col;
                    const __half* pc = e2 + (long long)z0 * e2s + (long long)r2 * ldc + col;
                    v0 = __half2float(pe[0]) * g0 + __half2float(pc[0]) * (1.0f - g0);
                    v1 = __half2float(pe[1]) * g1 + __half2float(pc[1]) * (1.0f - g1);
                }
                *reinterpret_cast<__half2*>(Cb + (long long)r2 * ldc + col) =
                    __floats2half2_rn(v0, v1);
            }
        }
    }
}

// ============== fp16 NN GEMM (cp.async + ldmatrix), fused ew epilogue ==============
template <int EW>
__global__ __launch_bounds__(256)
void nngemm_kernel(int K,
                   const __half* __restrict__ A, int lda, long long sA0, ZOffs aoffs,
                   const __half* __restrict__ B, int ldb, long long sB0, ZOffs boffs,
                   __half* __restrict__ C, int ldc, long long sC0, ZOffs coffs,
                   int nz0,
                   const __half* __restrict__ X, ZOffs xoffs, long long xs0,
                   __half* __restrict__ M, __half* __restrict__ Sb)
{
    extern __shared__ unsigned dsm[];
    const uint32_t sbb = (uint32_t)__cvta_generic_to_shared(dsm);

    const int z  = blockIdx.z;
    const int z1 = z / nz0;
    const int z0 = z - z1 * nz0;
    const __half* Ab = A + aoffs.o[z1] + (long long)z0 * sA0;
    const __half* Bb = B + boffs.o[z1] + (long long)z0 * sB0;

    const int bm = blockIdx.y * BM;
    const int bn = blockIdx.x * BN;
    const int tid  = threadIdx.x;
    const int lane = tid & 31;
    const int warp = tid >> 5;
    const int warpM = warp >> 2;
    const int warpN = warp & 3;
    const int g = lane >> 2;
    const int c = lane & 3;

    const int lrow  = tid >> 1;
    const int lpart = tid & 1;
    const int bkr = tid >> 3;
    const int bc8 = tid & 7;
    const int aRow = A_LANE_ROW, aCol = A_LANE_COL;

    const uint32_t lane_off = (uint32_t)(lane & 15) * (BNNP * 4) +
                              (uint32_t)(warpN * 32 + ((lane >> 4) << 3)) * 2;

    float cfr[4][4][4];
    #pragma unroll
    for (int mt = 0; mt < 4; ++mt)
        #pragma unroll
        for (int nt = 0; nt < 4; ++nt)
            #pragma unroll
            for (int r = 0; r < 4; ++r) cfr[mt][nt][r] = 0.0f;

    auto issue = [&](int s, int k0) {
        uint32_t ad = sbb + (uint32_t)((s * STG + lrow * ASTR + lpart * 8) * 4);
        const __half* ap = Ab + (long long)(bm + lrow) * lda + k0 + lpart * 16;
        cpa16(ad, ap); cpa16(ad + 16, ap + 8);
        uint32_t bd = sbb + (uint32_t)(((BOFF + s * NNSTG) + bkr * BNNP + bc8 * 8) * 4);
        const __half* bp = Bb + (long long)(k0 + bkr) * ldb + bn + bc8 * 16;
        cpa16(bd, bp); cpa16(bd + 16, bp + 8);
    };

    auto compute = [&](int s) {
        const uint32_t Au = sbb + (uint32_t)(s * STG * 4);
        const uint32_t bbuf = sbb + (uint32_t)((BOFF + s * NNSTG) * 4) + lane_off;
        #pragma unroll
        for (int kk = 0; kk < 2; ++kk) {
            unsigned af[4][4], bf[4][2];
            #pragma unroll
            for (int mt = 0; mt < 4; ++mt) {
                const uint32_t addr = Au +
                    (uint32_t)(((warpM * 64 + mt * 16 + aRow) * ASTR + kk * 8 + aCol) * 4);
                ldsm_x4(af[mt][0], af[mt][1], af[mt][2], af[mt][3], addr);
            }
            #pragma unroll
            for (int ntp = 0; ntp < 2; ++ntp) {
                const uint32_t addr = bbuf + (uint32_t)(kk * 16) * (BNNP * 4) + (uint32_t)(ntp * 32);
                ldsm_x4_trans(bf[2 * ntp][0], bf[2 * ntp][1], bf[2 * ntp + 1][0], bf[2 * ntp + 1][1], addr);
            }
            NT16_MMA()
        }
    };

    const int T = K / 32;
    issue(0, 0);  CP_COMMIT();
    issue(1, 32); CP_COMMIT();
    issue(2, 64); CP_COMMIT();
    for (int t = 0; t < T; ++t) {
        CP_WAIT2();
        __syncthreads();
        compute(t & 3);
        if (t + 3 < T) issue((t + 3) & 3, (t + 3) * 32);
        CP_COMMIT();
    }

    const long long cb = coffs.o[z1] + (long long)z0 * sC0;
    const __half* Xb = EW ? (X + xoffs.o[z1] + (long long)z0 * xs0) : nullptr;

    #pragma unroll
    for (int mt = 0; mt < 4; ++mt) {
        const int row = bm + warpM * 64 + mt * 16 + g;
        #pragma unroll
        for (int nt = 0; nt < 4; ++nt) {
            const int col = bn + warpN * 32 + nt * 8 + c * 2;
            #pragma unroll
            for (int half = 0; half < 2; ++half) {
                const int r2 = row + half * 8;
                const long long idx = cb + (long long)r2 * ldc + col;
                __half2 att = __floats2half2_rn(cfr[mt][nt][half * 2 + 0],
                                                cfr[mt][nt][half * 2 + 1]);
                if (EW == 0) {
                    *reinterpret_cast<__half2*>(C + idx) = att;
                } else {
                    const __half2 x = *reinterpret_cast<const __half2*>(Xb + (long long)r2 * ldc + col);
                    if (EW == 2) *reinterpret_cast<__half2*>(C + idx) = att;
                    *reinterpret_cast<__half2*>(M + idx)  = __hmul2(x, att);
                    *reinterpret_cast<__half2*>(Sb + idx) = __hsub2(x, att);
                }
            }
        }
    }
}

// ---------------- fp32 -> fp16 convert ----------------
__global__ void cvt_kernel(const float* __restrict__ src, __half* __restrict__ dst, long long n)
{
    long long i = ((long long)blockIdx.x * 256 + threadIdx.x) * 4;
    if (i < n) {
        float4 v = *reinterpret_cast<const float4*>(src + i);
        __half2 h0 = __floats2half2_rn(v.x, v.y);
        __half2 h1 = __floats2half2_rn(v.z, v.w);
        uint2 u;
        u.x = *reinterpret_cast<unsigned*>(&h0);
        u.y = *reinterpret_cast<unsigned*>(&h1);
        *reinterpret_cast<uint2*>(dst + i) = u;
    }
}

// ---------------- batched rowdot (half X, fp32 w) ----------------
__global__ void rowdot_kernel(const __half* __restrict__ X, ZOffs offs, int nz0, long long s0,
                              int ld, const float* __restrict__ w, float* __restrict__ out,
                              int rows, int Kd)
{
    __shared__ float sm[32];
    const int r = blockIdx.x, z = blockIdx.y;
    const int z1 = z / nz0, z0 = z - z1 * nz0;
    const __half* x = X + offs.o[z1] + (long long)z0 * s0 + (long long)r * ld;
    float s = 0.0f;
    for (int k = threadIdx.x; k < Kd; k += 256) s += __half2float(x[k]) * w[k];
    s = blockReduceSum(s, sm);
    if (threadIdx.x == 0) out[(long long)z * rows + r] = s;
}

// ---------------- row softmax: fp32 S in, fp16 P out (kl nullable) ----------------
__global__ void softmax_row_kernel(const float* __restrict__ S, __half* __restrict__ P,
                                   int ldS, long long strideS,
                                   const float* __restrict__ kl, ZOffs klo, long long kls0,
                                   int nz0, int Lk)
{
    __shared__ float sm[32];
    const int q = blockIdx.x, z = blockIdx.y;
    const int z1 = z / nz0, z0 = z - z1 * nz0;
    const float* row = S + (long long)z * strideS + (long long)q * ldS;
    __half* prow = P + (long long)z * strideS + (long long)q * ldS;
    const float* klb = kl ? (kl + klo.o[z1] + (long long)z0 * kls0) : nullptr;

    float v[3];
    int n = 0;
    float m = -3.4e38f;
    for (int k = threadIdx.x; k < Lk; k += 256) {
        float x = row[k] + (klb ? klb[k] : 0.0f);
        v[n++] = x;
        m = fmaxf(m, x);
    }
    m = blockReduceMax(m, sm);
    float s = 0.0f;
    for (int t = 0; t < n; ++t) { v[t] = expf(v[t] - m); s += v[t]; }
    s = blockReduceSum(s, sm);
    const float inv = 1.0f / s;
    n = 0;
    for (int k = threadIdx.x; k < Lk; k += 256) prow[k] = __float2half(v[n++] * inv);
}

// ---------------- column softmax (doc): fp32 S in, fp16 kq out ----------------
__global__ void softmax_col_kernel(const float* __restrict__ S, __half* __restrict__ kq,
                                   const float* __restrict__ ql)
{
    const int x = threadIdx.x & 31;
    const int y = threadIdx.x >> 5;
    const int col = blockIdx.x * 32 + x;
    const int z = blockIdx.y;
    const float* Sbb = S + (long long)z * (LO * LDOC);
    const float* qlb = ql + (long long)z * LO;

    float vals[LO / 8];
    float m = -3.4e38f;
    #pragma unroll 4
    for (int it = 0; it < LO / 8; ++it) {
        const int r = it * 8 + y;
        float v = qlb[r] + Sbb[(long long)r * LDOC + col];
        vals[it] = v;
        m = fmaxf(m, v);
    }
    __shared__ float red[8][32];
    red[y][x] = m;
    __syncthreads();
    if (y == 0) {
        float mm = red[0][x];
        #pragma unroll
        for (int t = 1; t < 8; ++t) mm = fmaxf(mm, red[t][x]);
        red[0][x] = mm;
    }
    __syncthreads();
    m = red[0][x];
    __syncthreads();

    float s = 0.0f;
    #pragma unroll 4
    for (int it = 0; it < LO / 8; ++it) { vals[it] = expf(vals[it] - m); s += vals[it]; }
    red[y][x] = s;
    __syncthreads();
    if (y == 0) {
        float ss = 0.0f;
        #pragma unroll
        for (int t = 0; t < 8; ++t) ss += red[t][x];
        red[0][x] = ss;
    }
    __syncthreads();
    const float inv = 1.0f / red[0][x];

    __half* kqb = kq + (long long)z * (LO * LDOC);
    #pragma unroll 4
    for (int it = 0; it < LO / 8; ++it)
        kqb[(long long)(it * 8 + y) * LDOC + col] = __float2half(vals[it] * inv);
}

// ---------------- final max over positions ----------------
__global__ void maxreduce_kernel(const __half* __restrict__ f, float* __restrict__ out)
{
    const int h = blockIdx.x * 256 + threadIdx.x;
    const int b = blockIdx.y;
    float m = -3.4e38f;
    const __half* base = f + (long long)b * LO * HD + h;
    #pragma unroll 8
    for (int r = 0; r < LO; ++r) m = fmaxf(m, __half2float(base[(long long)r * HD]));
    out[(long long)b * HD + h] = m;
}

// ---------------- host ----------------
static ZOffs zzero() { ZOffs z; for (int i = 0; i < 12; ++i) z.o[i] = 0; return z; }

extern "C" void kernel_launch(void* const* d_in, const int* in_sizes, int n_in,
                              void* d_out, int out_size)
{
    cudaFuncSetAttribute(tgemm_kernel<0, 0>, cudaFuncAttributeMaxDynamicSharedMemorySize, NT_SMEM);
    cudaFuncSetAttribute(tgemm_kernel<0, 1>, cudaFuncAttributeMaxDynamicSharedMemorySize, NT_SMEM);
    cudaFuncSetAttribute(tgemm_kernel<1, 0>, cudaFuncAttributeMaxDynamicSharedMemorySize, NT_SMEM);
    cudaFuncSetAttribute(segk_kernel, cudaFuncAttributeMaxDynamicSharedMemorySize, NT_SMEM);
    cudaFuncSetAttribute(nngemm_kernel<0>, cudaFuncAttributeMaxDynamicSharedMemorySize, NN_SMEM);
    cudaFuncSetAttribute(nngemm_kernel<1>, cudaFuncAttributeMaxDynamicSharedMemorySize, NN_SMEM);
    cudaFuncSetAttribute(nngemm_kernel<2>, cudaFuncAttributeMaxDynamicSharedMemorySize, NN_SMEM);

    const float* last   = (const float*)d_in[4];
    const float* ow2    = (const float*)d_in[6];
    const float* ow3    = (const float*)d_in[7];
    const float* dw1    = (const float*)d_in[8];
    const float* dw2    = (const float*)d_in[9];
    const float* dw3    = (const float*)d_in[10];
    const float* sw2    = (const float*)d_in[12];
    const float* sw3    = (const float*)d_in[13];
    const float* comp_w = (const float*)d_in[14];
    const float* comp_b = (const float*)d_in[15];
    const float* gate_w = (const float*)d_in[16];
    const float* gate_b = (const float*)d_in[17];
    const float* attn_w = (const float*)d_in[18];
    const float* attn_b = (const float*)d_in[19];
    const float* self_w = (const float*)d_in[20];
    const float* self_b = (const float*)d_in[21];

    float *S_, *kl_, *ql_;
    __half *hlast, *hmul, *hsub, *hP, *hkq, *hcow, *hcorr, *hopt, *ha, *hco, *hfus, *hsa, *hfm, *hfs;
    __half *hcompw, *hgatew, *hattnw, *hselfw, *haff;
    cudaGetSymbolAddress((void**)&S_,  g_S);
    cudaGetSymbolAddress((void**)&kl_, g_kl);
    cudaGetSymbolAddress((void**)&ql_, g_ql);
    cudaGetSymbolAddress((void**)&hlast, h_last);
    cudaGetSymbolAddress((void**)&hmul,  h_mul);
    cudaGetSymbolAddress((void**)&hsub,  h_sub);
    cudaGetSymbolAddress((void**)&hP,    h_P);
    cudaGetSymbolAddress((void**)&hkq,   h_kq);
    cudaGetSymbolAddress((void**)&hcow,  h_cow);
    cudaGetSymbolAddress((void**)&hcorr, h_corr);
    cudaGetSymbolAddress((void**)&hopt,  h_opt);
    cudaGetSymbolAddress((void**)&ha,    h_a);
    cudaGetSymbolAddress((void**)&hco,   h_co);
    cudaGetSymbolAddress((void**)&hfus,  h_fus);
    cudaGetSymbolAddress((void**)&hsa,   h_sa);
    cudaGetSymbolAddress((void**)&hfm,   h_fm);
    cudaGetSymbolAddress((void**)&hfs,   h_fs);
    cudaGetSymbolAddress((void**)&hcompw, h_compw);
    cudaGetSymbolAddress((void**)&hgatew, h_gatew);
    cudaGetSymbolAddress((void**)&hattnw, h_attnw);
    cudaGetSymbolAddress((void**)&hselfw, h_selfw);
    cudaGetSymbolAddress((void**)&haff,   h_aff);

    const long long sSeq = (long long)SEQ * HD;
    const long long sQ   = 4LL * SEQ * HD;
    const long long LoH  = (long long)LO * HD;

    // ===== input conversions =====
    cvt_kernel<<<(NBAT * (long long)SEQ * HD) / 1024, 256>>>(last, hlast, (long long)NBAT * SEQ * HD);
    cvt_kernel<<<(7LL * HD * HD) / 1024, 256>>>(comp_w, hcompw, 7LL * HD * HD);
    cvt_kernel<<<(2LL * HD * HD) / 1024, 256>>>(gate_w, hgatew, 2LL * HD * HD);
    cvt_kernel<<<(3LL * HD * HD) / 1024, 256>>>(attn_w, hattnw, 3LL * HD * HD);
    cvt_kernel<<<(4LL * HD * HD) / 1024, 256>>>(self_w, hselfw, 4LL * HD * HD);
    cvt_kernel<<<1, 256>>>(ow3, haff + 0 * HD, HD);
    cvt_kernel<<<1, 256>>>(ow2, haff + 1 * HD, HD);
    cvt_kernel<<<1, 256>>>(sw3, haff + 2 * HD, HD);
    cvt_kernel<<<1, 256>>>(sw2, haff + 3 * HD, HD);

    long long curoff[NL], kvoff[12];
    for (int i = 0; i < NL; ++i) curoff[i] = ((long long)i * SEQ + LDOC) * HD;
    for (int i = 0, p = 0; i < NL; ++i)
        for (int j = 0; j < NL; ++j) {
            if (j == i) continue;
            kvoff[p] = ((long long)j * SEQ + LDOC) * HD;
            ++p;
        }

    // ===== Stage A: 12 pair attentions (kl folded into A-affine) =====
    {
        ZOffs kvo = zzero(), ao = zzero(), co = zzero();
        for (int p = 0; p < 12; ++p) {
            kvo.o[p] = kvoff[p];
            ao.o[p] = curoff[p / 3];
            co.o[p] = (long long)p * NBZ * LO * LO;
        }
        tgemm_kernel<0, 1><<<dim3(LO / BN, LO / BM, 96), 256, NT_SMEM>>>(
            HD, hlast, HD, sQ, ao, hlast, HD, sQ, kvo,
            S_, LO, (long long)LO * LO, co, NBZ, nullptr,
            haff + 0 * HD, haff + 1 * HD);

        softmax_row_kernel<<<dim3(LO, 96), 256>>>(S_, hP, LO, (long long)LO * LO,
                                                  nullptr, zzero(), 0, NBZ, LO);

        ZOffs ato = zzero(), xo = zzero();
        for (int p = 0; p < 12; ++p) { ato.o[p] = (long long)p * NBZ * LoH; xo.o[p] = curoff[p / 3]; }
        nngemm_kernel<1><<<dim3(HD / BN, LO / BM, 96), 256, NN_SMEM>>>(
            LO, hP, LO, (long long)LO * LO, co, hlast, HD, sQ, kvo,
            nullptr, HD, LoH, ato, NBZ,
            hlast, xo, sQ, hmul, hsub);
    }

    // ===== comp: segmented GEMM K=7168 =====
    {
        HSegArgs sga = {};
        sga.segs[0] = {hlast, (long long)LDOC * HD, (long long)SEQ * HD, sQ};
        for (int m = 0; m < 3; ++m) {
            sga.segs[1 + 2 * m] = {hmul, (long long)m * NBZ * LoH, 3LL * NBZ * LoH, LoH};
            sga.segs[2 + 2 * m] = {hsub, (long long)m * NBZ * LoH, 3LL * NBZ * LoH, LoH};
        }
        sga.nseg = 7;
        ZOffs co = zzero();
        for (int i = 0; i < NL; ++i) co.o[i] = (long long)i * LoH;
        segk_kernel<<<dim3(HD / BN, LO / BM, 32), 256, NT_SMEM>>>(
            7 * HD, sga, hcompw, 7 * HD,
            hcorr, HD, 4 * LoH, co, NBZ,
            comp_b, 2, nullptr, 0, nullptr, 0);
    }

    // ===== Stage B: gate + blend -> opt =====
    {
        HSegArgs sga = {};
        sga.segs[0] = {hlast, (long long)LDOC * HD, 0, sSeq};
        sga.segs[1] = {hcorr, 0, 0, LoH};
        sga.nseg = 2;
        segk_kernel<<<dim3(HD / BN, LO / BM, 32), 256, NT_SMEM>>>(
            2 * HD, sga, hgatew, 2 * HD,
            hopt, HD, LoH, zzero(), NBAT,
            gate_b, 4, hlast + (long long)LDOC * HD, sSeq, hcorr, LoH);
    }

    // ===== Stage C: doc attention (needs raw S for both softmaxes) =====
    {
        ZOffs z0o = zzero();
        rowdot_kernel<<<dim3(LO, NBAT), 256>>>(hopt, z0o, NBAT, LoH, HD, dw1, ql_, LO, HD);
        rowdot_kernel<<<dim3(LDOC, NBAT), 256>>>(hlast, z0o, NBAT, sSeq, HD, dw2, kl_, LDOC, HD);

        tgemm_kernel<0, 0><<<dim3(LDOC / BN, LO / BM, 32), 256, NT_SMEM>>>(
            HD, hopt, HD, LoH, zzero(), hlast, HD, sSeq, zzero(),
            S_, LDOC, (long long)LO * LDOC, zzero(), NBAT, dw3, nullptr, nullptr);

        softmax_col_kernel<<<dim3(LDOC / 32, NBAT), 256>>>(S_, hkq, ql_);
        softmax_row_kernel<<<dim3(LO, NBAT), 256>>>(S_, hP, LDOC, (long long)LO * LDOC,
                                                    kl_, zzero(), LDOC, NBAT, LDOC);

        nngemm_kernel<0><<<dim3(HD / BN, LO / BM, 32), 256, NN_SMEM>>>(
            LDOC, hP, LDOC, (long long)LO * LDOC, zzero(), hlast, HD, sSeq, zzero(),
            ha, HD, LoH, zzero(), NBAT,
            nullptr, zzero(), 0, nullptr, nullptr);

        tgemm_kernel<1, 0><<<dim3(LO / BN, LO / BM, 32), 256, NT_SMEM>>>(
            LDOC, hP, LDOC, (long long)LO * LDOC, zzero(), hkq, LDOC, (long long)LO * LDOC, zzero(),
            hcow, LO, (long long)LO * LO, zzero(), NBAT, nullptr, nullptr, nullptr);

        nngemm_kernel<0><<<dim3(HD / BN, LO / BM, 32), 256, NN_SMEM>>>(
            LO, hcow, LO, (long long)LO * LO, zzero(), hopt, HD, LoH, zzero(),
            hco, HD, LoH, zzero(), NBAT,
            nullptr, zzero(), 0, nullptr, nullptr);
    }

    // ===== Stage D: fusion =====
    {
        HSegArgs sga = {};
        sga.segs[0] = {hopt, 0, 0, LoH};
        sga.segs[1] = {ha,   0, 0, LoH};
        sga.segs[2] = {hco,  0, 0, LoH};
        sga.nseg = 3;
        segk_kernel<<<dim3(HD / BN, LO / BM, 32), 256, NT_SMEM>>>(
            3 * HD, sga, hattnw, 3 * HD,
            hfus, HD, LoH, zzero(), NBAT,
            attn_b, 1, nullptr, 0, nullptr, 0);
    }

    // ===== Stage E: self attention (kl folded into A-affine) =====
    {
        tgemm_kernel<0, 1><<<dim3(LO / BN, LO / BM, 32), 256, NT_SMEM>>>(
            HD, hfus, HD, LoH, zzero(), hfus, HD, LoH, zzero(),
            S_, LO, (long long)LO * LO, zzero(), NBAT, nullptr,
            haff + 2 * HD, haff + 3 * HD);

        softmax_row_kernel<<<dim3(LO, NBAT), 256>>>(S_, hP, LO, (long long)LO * LO,
                                                    nullptr, zzero(), 0, NBAT, LO);

        nngemm_kernel<2><<<dim3(HD / BN, LO / BM, 32), 256, NN_SMEM>>>(
            LO, hP, LO, (long long)LO * LO, zzero(), hfus, HD, LoH, zzero(),
            hsa, HD, LoH, zzero(), NBAT,
            hfus, zzero(), LoH, hfm, hfs);
    }

    // ===== Stage F: fusion2 =====
    {
        HSegArgs sga = {};
        sga.segs[0] = {hfus, 0, 0, LoH};
        sga.segs[1] = {hsa,  0, 0, LoH};
        sga.segs[2] = {hfm,  0, 0, LoH};
        sga.segs[3] = {hfs,  0, 0, LoH};
        sga.nseg = 4;
        segk_kernel<<<dim3(HD / BN, LO / BM, 32), 256, NT_SMEM>>>(
            4 * HD, sga, hselfw, 4 * HD,
            hcorr, HD, LoH, zzero(), NBAT,
            self_b, 1, nullptr, 0, nullptr, 0);
    }

    // ===== Stage G =====
    maxreduce_kernel<<<dim3(HD / 256, NBAT), 256>>>(hcorr, (float*)d_out);
}

// round 17
// speedup vs baseline: 1.3767x; 1.3767x over previous
#include <cuda_runtime.h>
#include <cuda_fp16.h>
#include <math.h>
#include <stdint.h>

#define HD   1024
#define SEQ  1024
#define LO   256
#define LDOC 768
#define NBAT 32
#define NBZ  8
#define NL   4

// ---------------- fp32 scratch ----------------
__device__ float g_S [96 * LO * LO];
__device__ float g_kl[NBAT * LDOC];
__device__ float g_ql[NBAT * LO];

// ---------------- fp16 buffers ----------------
__device__ __half h_last [NBAT * SEQ * HD];
__device__ __half h_mul  [96 * LO * HD];
__device__ __half h_sub  [96 * LO * HD];
__device__ __half h_P    [96 * LO * LO];
__device__ __half h_kq   [NBAT * LO * LDOC];
__device__ __half h_cow  [NBAT * LO * LO];
__device__ __half h_corr [NBAT * LO * HD];
__device__ __half h_opt  [NBAT * LO * HD];
__device__ __half h_a    [NBAT * LO * HD];
__device__ __half h_co   [NBAT * LO * HD];
__device__ __half h_fus  [NBAT * LO * HD];
__device__ __half h_sa   [NBAT * LO * HD];
__device__ __half h_fm   [NBAT * LO * HD];
__device__ __half h_fs   [NBAT * LO * HD];
__device__ __half h_compw[7 * HD * HD];
__device__ __half h_gatew[2 * HD * HD];
__device__ __half h_attnw[3 * HD * HD];
__device__ __half h_selfw[4 * HD * HD];
__device__ __half h_aff  [4 * HD];   // [ow3 | ow2 | sw3 | sw2]

struct ZOffs { long long o[12]; };
struct HSeg  { const __half* A; long long c0, c1, s0; };
struct HSegArgs { HSeg segs[8]; int nseg; };

// ---------------- helpers ----------------
__device__ __forceinline__ void cpa16(uint32_t dst, const void* src) {
    asm volatile("cp.async.cg.shared.global [%0], [%1], 16;" :: "r"(dst), "l"(src));
}
#define CP_COMMIT() asm volatile("cp.async.commit_group;" ::: "memory")
#define CP_WAIT2()  asm volatile("cp.async.wait_group 2;" ::: "memory")

__device__ __forceinline__ unsigned hscale2u(unsigned a, __half2 s) {
    __half2 x = __hmul2(*reinterpret_cast<__half2*>(&a), s);
    return *reinterpret_cast<unsigned*>(&x);
}
__device__ __forceinline__ unsigned hfma2u(unsigned a, __half2 s, __half2 o) {
    __half2 x = __hfma2(*reinterpret_cast<__half2*>(&a), s, o);
    return *reinterpret_cast<unsigned*>(&x);
}

__device__ __forceinline__ void ldsm_x4_trans(unsigned& r0, unsigned& r1, unsigned& r2, unsigned& r3,
                                              uint32_t addr) {
    asm volatile("ldmatrix.sync.aligned.m8n8.x4.trans.shared.b16 {%0,%1,%2,%3}, [%4];"
                 : "=r"(r0), "=r"(r1), "=r"(r2), "=r"(r3) : "r"(addr));
}

__device__ __forceinline__ float blockReduceMax(float v, float* sm) {
    #pragma unroll
    for (int o = 16; o; o >>= 1) v = fmaxf(v, __shfl_xor_sync(0xffffffffu, v, o));
    int w = threadIdx.x >> 5;
    if ((threadIdx.x & 31) == 0) sm[w] = v;
    __syncthreads();
    if (threadIdx.x < 32) {
        v = (threadIdx.x < (blockDim.x >> 5)) ? sm[threadIdx.x] : -3.4e38f;
        #pragma unroll
        for (int o = 4; o; o >>= 1) v = fmaxf(v, __shfl_xor_sync(0xffffffffu, v, o));
        if (threadIdx.x == 0) sm[0] = v;
    }
    __syncthreads();
    v = sm[0];
    __syncthreads();
    return v;
}

__device__ __forceinline__ float blockReduceSum(float v, float* sm) {
    #pragma unroll
    for (int o = 16; o; o >>= 1) v += __shfl_xor_sync(0xffffffffu, v, o);
    int w = threadIdx.x >> 5;
    if ((threadIdx.x & 31) == 0) sm[w] = v;
    __syncthreads();
    if (threadIdx.x < 32) {
        v = (threadIdx.x < (blockDim.x >> 5)) ? sm[threadIdx.x] : 0.0f;
        #pragma unroll
        for (int o = 4; o; o >>= 1) v += __shfl_xor_sync(0xffffffffu, v, o);
        if (threadIdx.x == 0) sm[0] = v;
    }
    __syncthreads();
    v = sm[0];
    __syncthreads();
    return v;
}

#define BM 128
#define BN 128
#define ASTR 20
#define STG 2560
#define BOFF 10240
#define BNNP 68
#define NNSTG 2176
#define NT_SMEM 81920
#define NN_SMEM 75776

#define NT16_LOAD_A(Au)                                                  \
    _Pragma("unroll")                                                    \
    for (int mt = 0; mt < 4; ++mt) {                                     \
        const int r0 = (warpM * 64 + mt * 16 + g) * ASTR + kk * 8 + c;   \
        af[mt][0] = Au[r0];                                              \
        af[mt][1] = Au[r0 + 8 * ASTR];                                   \
        af[mt][2] = Au[r0 + 4];                                          \
        af[mt][3] = Au[r0 + 8 * ASTR + 4];                               \
    }

#define NT16_MMA()                                                                   \
    _Pragma("unroll")                                                                \
    for (int mt = 0; mt < 4; ++mt)                                                   \
        _Pragma("unroll")                                                            \
        for (int nt = 0; nt < 4; ++nt) {                                             \
            asm volatile(                                                            \
                "mma.sync.aligned.m16n8k16.row.col.f32.f16.f16.f32 "                 \
                "{%0,%1,%2,%3}, {%4,%5,%6,%7}, {%8,%9}, {%0,%1,%2,%3};"              \
                : "+f"(cfr[mt][nt][0]), "+f"(cfr[mt][nt][1]),                        \
                  "+f"(cfr[mt][nt][2]), "+f"(cfr[mt][nt][3])                         \
                : "r"(af[mt][0]), "r"(af[mt][1]), "r"(af[mt][2]), "r"(af[mt][3]),    \
                  "r"(bf[nt][0]), "r"(bf[nt][1]));                                   \
        }

// ================= fp16 NT GEMM (cp.async 4-stage, LDS frags) =======================
// AFF=1: A-fragment affine a' = s*a + o (fp16 k-vectors). bscale: fp32 B k-scale.
template <int OUT16, int AFF>
__global__ __launch_bounds__(256)
void tgemm_kernel(int K,
                  const __half* __restrict__ A, int lda, long long sA0, ZOffs aoffs,
                  const __half* __restrict__ B, int ldb, long long sB0, ZOffs boffs,
                  void* __restrict__ Cv, int ldc, long long sC0, ZOffs coffs,
                  int nz0, const float* __restrict__ bscale,
                  const __half* __restrict__ aff_s, const __half* __restrict__ aff_o)
{
    extern __shared__ unsigned dsm[];
    const uint32_t sb = (uint32_t)__cvta_generic_to_shared(dsm);

    const int z  = blockIdx.z;
    const int z1 = z / nz0;
    const int z0 = z - z1 * nz0;
    const __half* Ab = A + aoffs.o[z1] + (long long)z0 * sA0;
    const __half* Bb = B + boffs.o[z1] + (long long)z0 * sB0;

    const int bm = blockIdx.y * BM;
    const int bn = blockIdx.x * BN;
    const int tid  = threadIdx.x;
    const int lane = tid & 31;
    const int warp = tid >> 5;
    const int warpM = warp >> 2;
    const int warpN = warp & 3;
    const int g = lane >> 2;
    const int c = lane & 3;

    const int lrow  = tid >> 1;
    const int lpart = tid & 1;

    const __half2* hs = AFF ? reinterpret_cast<const __half2*>(aff_s) : nullptr;
    const __half2* ho = AFF ? reinterpret_cast<const __half2*>(aff_o) : nullptr;

    float cfr[4][4][4];
    #pragma unroll
    for (int mt = 0; mt < 4; ++mt)
        #pragma unroll
        for (int nt = 0; nt < 4; ++nt)
            #pragma unroll
            for (int r = 0; r < 4; ++r) cfr[mt][nt][r] = 0.0f;

    auto issue = [&](int s, int k0) {
        uint32_t ad = sb + (uint32_t)((s * STG + lrow * ASTR + lpart * 8) * 4);
        const __half* ap = Ab + (long long)(bm + lrow) * lda + k0 + lpart * 16;
        cpa16(ad, ap); cpa16(ad + 16, ap + 8);
        uint32_t bd = sb + (uint32_t)(((BOFF + s * STG) + lrow * ASTR + lpart * 8) * 4);
        const __half* bp = Bb + (long long)(bn + lrow) * ldb + k0 + lpart * 16;
        cpa16(bd, bp); cpa16(bd + 16, bp + 8);
    };

    auto compute = [&](int s, int k0) {
        const unsigned* Au = dsm + s * STG;
        const unsigned* Bu = dsm + BOFF + s * STG;
        #pragma unroll
        for (int kk = 0; kk < 2; ++kk) {
            unsigned af[4][4], bf[4][2];
            NT16_LOAD_A(Au)
            #pragma unroll
            for (int nt = 0; nt < 4; ++nt) {
                const int n0 = warpN * 32 + nt * 8 + g;
                bf[nt][0] = Bu[n0 * ASTR + kk * 8 + c];
                bf[nt][1] = Bu[n0 * ASTR + kk * 8 + c + 4];
            }
            if (AFF) {
                const int kb = (k0 >> 1) + kk * 8 + c;
                const __half2 s0 = hs[kb],     o0 = ho[kb];
                const __half2 s1 = hs[kb + 4], o1 = ho[kb + 4];
                #pragma unroll
                for (int mt = 0; mt < 4; ++mt) {
                    af[mt][0] = hfma2u(af[mt][0], s0, o0);
                    af[mt][1] = hfma2u(af[mt][1], s0, o0);
                    af[mt][2] = hfma2u(af[mt][2], s1, o1);
                    af[mt][3] = hfma2u(af[mt][3], s1, o1);
                }
            }
            if (bscale) {
                const int kb = k0 + kk * 16 + 2 * c;
                __half2 s0 = __floats2half2_rn(bscale[kb], bscale[kb + 1]);
                __half2 s1 = __floats2half2_rn(bscale[kb + 8], bscale[kb + 9]);
                #pragma unroll
                for (int nt = 0; nt < 4; ++nt) {
                    bf[nt][0] = hscale2u(bf[nt][0], s0);
                    bf[nt][1] = hscale2u(bf[nt][1], s1);
                }
            }
            NT16_MMA()
        }
    };

    const int T = K / 32;
    issue(0, 0);  CP_COMMIT();
    issue(1, 32); CP_COMMIT();
    issue(2, 64); CP_COMMIT();
    for (int t = 0; t < T; ++t) {
        CP_WAIT2();
        __syncthreads();
        compute(t & 3, t * 32);
        if (t + 3 < T) issue((t + 3) & 3, (t + 3) * 32);
        CP_COMMIT();
    }

    #pragma unroll
    for (int mt = 0; mt < 4; ++mt) {
        const int row = bm + warpM * 64 + mt * 16 + g;
        #pragma unroll
        for (int nt = 0; nt < 4; ++nt) {
            const int col = bn + warpN * 32 + nt * 8 + c * 2;
            #pragma unroll
            for (int half = 0; half < 2; ++half) {
                const int r2 = row + half * 8;
                float v0 = cfr[mt][nt][half * 2 + 0];
                float v1 = cfr[mt][nt][half * 2 + 1];
                if (OUT16) {
                    __half* Ch = (__half*)Cv + coffs.o[z1] + (long long)z0 * sC0;
                    *reinterpret_cast<__half2*>(Ch + (long long)r2 * ldc + col) =
                        __floats2half2_rn(v0, v1);
                } else {
                    float* Cf = (float*)Cv + coffs.o[z1] + (long long)z0 * sC0;
                    float* p = Cf + (long long)r2 * ldc + col;
                    p[0] = v0; p[1] = v1;
                }
            }
        }
    }
}

// ================= fp16 segmented-K NT GEMM (cp.async 4-stage, fused epilogue) ======
__global__ __launch_bounds__(256)
void segk_kernel(int Ktot, HSegArgs sga,
                 const __half* __restrict__ B, int ldb,
                 __half* __restrict__ C, int ldc, long long sC0, ZOffs coffs, int nz0,
                 const float* __restrict__ bias, int act,
                 const __half* __restrict__ e1, long long e1s,
                 const __half* __restrict__ e2, long long e2s)
{
    extern __shared__ unsigned dsm[];
    const uint32_t sb = (uint32_t)__cvta_generic_to_shared(dsm);

    const int z  = blockIdx.z;
    const int z1 = z / nz0;
    const int z0 = z - z1 * nz0;
    __half* Cb = C + coffs.o[z1] + (long long)z0 * sC0;

    const int bm = blockIdx.y * BM;
    const int bn = blockIdx.x * BN;
    const int tid  = threadIdx.x;
    const int lane = tid & 31;
    const int warp = tid >> 5;
    const int warpM = warp >> 2;
    const int warpN = warp & 3;
    const int g = lane >> 2;
    const int c = lane & 3;

    const int lrow  = tid >> 1;
    const int lpart = tid & 1;

    int curseg = -1;
    const __half* Ab = nullptr;

    float cfr[4][4][4];
    #pragma unroll
    for (int mt = 0; mt < 4; ++mt)
        #pragma unroll
        for (int nt = 0; nt < 4; ++nt)
            #pragma unroll
            for (int r = 0; r < 4; ++r) cfr[mt][nt][r] = 0.0f;

    auto issue = [&](int s, int k0) {
        const int sg = k0 >> 10;
        if (sg != curseg) {
            curseg = sg;
            const HSeg& h = sga.segs[sg];
            Ab = h.A + h.c0 + h.c1 * z1 + h.s0 * z0;
        }
        const int kl = k0 & 1023;
        uint32_t ad = sb + (uint32_t)((s * STG + lrow * ASTR + lpart * 8) * 4);
        const __half* ap = Ab + (long long)(bm + lrow) * 1024 + kl + lpart * 16;
        cpa16(ad, ap); cpa16(ad + 16, ap + 8);
        uint32_t bd = sb + (uint32_t)(((BOFF + s * STG) + lrow * ASTR + lpart * 8) * 4);
        const __half* bp = B + (long long)(bn + lrow) * ldb + k0 + lpart * 16;
        cpa16(bd, bp); cpa16(bd + 16, bp + 8);
    };

    auto compute = [&](int s) {
        const unsigned* Au = dsm + s * STG;
        const unsigned* Bu = dsm + BOFF + s * STG;
        #pragma unroll
        for (int kk = 0; kk < 2; ++kk) {
            unsigned af[4][4], bf[4][2];
            NT16_LOAD_A(Au)
            #pragma unroll
            for (int nt = 0; nt < 4; ++nt) {
                const int n0 = warpN * 32 + nt * 8 + g;
                bf[nt][0] = Bu[n0 * ASTR + kk * 8 + c];
                bf[nt][1] = Bu[n0 * ASTR + kk * 8 + c + 4];
            }
            NT16_MMA()
        }
    };

    const int T = Ktot / 32;
    issue(0, 0);  CP_COMMIT();
    issue(1, 32); CP_COMMIT();
    issue(2, 64); CP_COMMIT();
    for (int t = 0; t < T; ++t) {
        CP_WAIT2();
        __syncthreads();
        compute(t & 3);
        if (t + 3 < T) issue((t + 3) & 3, (t + 3) * 32);
        CP_COMMIT();
    }

    #pragma unroll
    for (int mt = 0; mt < 4; ++mt) {
        const int row = bm + warpM * 64 + mt * 16 + g;
        #pragma unroll
        for (int nt = 0; nt < 4; ++nt) {
            const int col = bn + warpN * 32 + nt * 8 + c * 2;
            #pragma unroll
            for (int half = 0; half < 2; ++half) {
                const int r2 = row + half * 8;
                float v0 = cfr[mt][nt][half * 2 + 0];
                float v1 = cfr[mt][nt][half * 2 + 1];
                if (bias) { v0 += bias[col]; v1 += bias[col + 1]; }
                if (act == 1)      { v0 = fmaxf(v0, 0.0f); v1 = fmaxf(v1, 0.0f); }
                else if (act == 2) { v0 = tanhf(v0); v1 = tanhf(v1); }
                else if (act == 4) {
                    const float g0 = 1.0f / (1.0f + expf(-v0));
                    const float g1 = 1.0f / (1.0f + expf(-v1));
                    const __half* pe = e1 + (long long)z0 * e1s + (long long)r2 * ldc + col;
                    const __half* pc = e2 + (long long)z0 * e2s + (long long)r2 * ldc + col;
                    v0 = __half2float(pe[0]) * g0 + __half2float(pc[0]) * (1.0f - g0);
                    v1 = __half2float(pe[1]) * g1 + __half2float(pc[1]) * (1.0f - g1);
                }
                *reinterpret_cast<__half2*>(Cb + (long long)r2 * ldc + col) =
                    __floats2half2_rn(v0, v1);
            }
        }
    }
}

// ============== fp16 NN GEMM (cp.async + ldmatrix.trans), fused ew epilogue =========
template <int EW>
__global__ __launch_bounds__(256)
void nngemm_kernel(int K,
                   const __half* __restrict__ A, int lda, long long sA0, ZOffs aoffs,
                   const __half* __restrict__ B, int ldb, long long sB0, ZOffs boffs,
                   __half* __restrict__ C, int ldc, long long sC0, ZOffs coffs,
                   int nz0,
                   const __half* __restrict__ X, ZOffs xoffs, long long xs0,
                   __half* __restrict__ M, __half* __restrict__ Sb)
{
    extern __shared__ unsigned dsm[];
    const uint32_t sbb = (uint32_t)__cvta_generic_to_shared(dsm);

    const int z  = blockIdx.z;
    const int z1 = z / nz0;
    const int z0 = z - z1 * nz0;
    const __half* Ab = A + aoffs.o[z1] + (long long)z0 * sA0;
    const __half* Bb = B + boffs.o[z1] + (long long)z0 * sB0;

    const int bm = blockIdx.y * BM;
    const int bn = blockIdx.x * BN;
    const int tid  = threadIdx.x;
    const int lane = tid & 31;
    const int warp = tid >> 5;
    const int warpM = warp >> 2;
    const int warpN = warp & 3;
    const int g = lane >> 2;
    const int c = lane & 3;

    const int lrow  = tid >> 1;
    const int lpart = tid & 1;
    const int bkr = tid >> 3;
    const int bc8 = tid & 7;

    const uint32_t lane_off = (uint32_t)(lane & 15) * (BNNP * 4) +
                              (uint32_t)(warpN * 32 + ((lane >> 4) << 3)) * 2;

    float cfr[4][4][4];
    #pragma unroll
    for (int mt = 0; mt < 4; ++mt)
        #pragma unroll
        for (int nt = 0; nt < 4; ++nt)
            #pragma unroll
            for (int r = 0; r < 4; ++r) cfr[mt][nt][r] = 0.0f;

    auto issue = [&](int s, int k0) {
        uint32_t ad = sbb + (uint32_t)((s * STG + lrow * ASTR + lpart * 8) * 4);
        const __half* ap = Ab + (long long)(bm + lrow) * lda + k0 + lpart * 16;
        cpa16(ad, ap); cpa16(ad + 16, ap + 8);
        uint32_t bd = sbb + (uint32_t)(((BOFF + s * NNSTG) + bkr * BNNP + bc8 * 8) * 4);
        const __half* bp = Bb + (long long)(k0 + bkr) * ldb + bn + bc8 * 16;
        cpa16(bd, bp); cpa16(bd + 16, bp + 8);
    };

    auto compute = [&](int s) {
        const unsigned* Au = dsm + s * STG;
        const uint32_t bbuf = sbb + (uint32_t)((BOFF + s * NNSTG) * 4) + lane_off;
        #pragma unroll
        for (int kk = 0; kk < 2; ++kk) {
            unsigned af[4][4], bf[4][2];
            NT16_LOAD_A(Au)
            #pragma unroll
            for (int ntp = 0; ntp < 2; ++ntp) {
                const uint32_t addr = bbuf + (uint32_t)(kk * 16) * (BNNP * 4) + (uint32_t)(ntp * 32);
                ldsm_x4_trans(bf[2 * ntp][0], bf[2 * ntp][1], bf[2 * ntp + 1][0], bf[2 * ntp + 1][1], addr);
            }
            NT16_MMA()
        }
    };

    const int T = K / 32;
    issue(0, 0);  CP_COMMIT();
    issue(1, 32); CP_COMMIT();
    issue(2, 64); CP_COMMIT();
    for (int t = 0; t < T; ++t) {
        CP_WAIT2();
        __syncthreads();
        compute(t & 3);
        if (t + 3 < T) issue((t + 3) & 3, (t + 3) * 32);
        CP_COMMIT();
    }

    const long long cb = coffs.o[z1] + (long long)z0 * sC0;
    const __half* Xb = EW ? (X + xoffs.o[z1] + (long long)z0 * xs0) : nullptr;

    #pragma unroll
    for (int mt = 0; mt < 4; ++mt) {
        const int row = bm + warpM * 64 + mt * 16 + g;
        #pragma unroll
        for (int nt = 0; nt < 4; ++nt) {
            const int col = bn + warpN * 32 + nt * 8 + c * 2;
            #pragma unroll
            for (int half = 0; half < 2; ++half) {
                const int r2 = row + half * 8;
                const long long idx = cb + (long long)r2 * ldc + col;
                __half2 att = __floats2half2_rn(cfr[mt][nt][half * 2 + 0],
                                                cfr[mt][nt][half * 2 + 1]);
                if (EW == 0) {
                    *reinterpret_cast<__half2*>(C + idx) = att;
                } else {
                    const __half2 x = *reinterpret_cast<const __half2*>(Xb + (long long)r2 * ldc + col);
                    if (EW == 2) *reinterpret_cast<__half2*>(C + idx) = att;
                    *reinterpret_cast<__half2*>(M + idx)  = __hmul2(x, att);
                    *reinterpret_cast<__half2*>(Sb + idx) = __hsub2(x, att);
                }
            }
        }
    }
}

// ---------------- fp32 -> fp16 convert ----------------
__global__ void cvt_kernel(const float* __restrict__ src, __half* __restrict__ dst, long long n)
{
    long long i = ((long long)blockIdx.x * 256 + threadIdx.x) * 4;
    if (i < n) {
        float4 v = *reinterpret_cast<const float4*>(src + i);
        __half2 h0 = __floats2half2_rn(v.x, v.y);
        __half2 h1 = __floats2half2_rn(v.z, v.w);
        uint2 u;
        u.x = *reinterpret_cast<unsigned*>(&h0);
        u.y = *reinterpret_cast<unsigned*>(&h1);
        *reinterpret_cast<uint2*>(dst + i) = u;
    }
}

// ---------------- batched rowdot (half X, fp32 w) ----------------
__global__ void rowdot_kernel(const __half* __restrict__ X, ZOffs offs, int nz0, long long s0,
                              int ld, const float* __restrict__ w, float* __restrict__ out,
                              int rows, int Kd)
{
    __shared__ float sm[32];
    const int r = blockIdx.x, z = blockIdx.y;
    const int z1 = z / nz0, z0 = z - z1 * nz0;
    const __half* x = X + offs.o[z1] + (long long)z0 * s0 + (long long)r * ld;
    float s = 0.0f;
    for (int k = threadIdx.x; k < Kd; k += 256) s += __half2float(x[k]) * w[k];
    s = blockReduceSum(s, sm);
    if (threadIdx.x == 0) out[(long long)z * rows + r] = s;
}

// ---------------- row softmax: fp32 S in, fp16 P out (kl nullable) ----------------
__global__ void softmax_row_kernel(const float* __restrict__ S, __half* __restrict__ P,
                                   int ldS, long long strideS,
                                   const float* __restrict__ kl, ZOffs klo, long long kls0,
                                   int nz0, int Lk)
{
    __shared__ float sm[32];
    const int q = blockIdx.x, z = blockIdx.y;
    const int z1 = z / nz0, z0 = z - z1 * nz0;
    const float* row = S + (long long)z * strideS + (long long)q * ldS;
    __half* prow = P + (long long)z * strideS + (long long)q * ldS;
    const float* klb = kl ? (kl + klo.o[z1] + (long long)z0 * kls0) : nullptr;

    float v[3];
    int n = 0;
    float m = -3.4e38f;
    for (int k = threadIdx.x; k < Lk; k += 256) {
        float x = row[k] + (klb ? klb[k] : 0.0f);
        v[n++] = x;
        m = fmaxf(m, x);
    }
    m = blockReduceMax(m, sm);
    float s = 0.0f;
    for (int t = 0; t < n; ++t) { v[t] = expf(v[t] - m); s += v[t]; }
    s = blockReduceSum(s, sm);
    const float inv = 1.0f / s;
    n = 0;
    for (int k = threadIdx.x; k < Lk; k += 256) prow[k] = __float2half(v[n++] * inv);
}

// ---------------- column softmax (doc): fp32 S in, fp16 kq out ----------------
__global__ void softmax_col_kernel(const float* __restrict__ S, __half* __restrict__ kq,
                                   const float* __restrict__ ql)
{
    const int x = threadIdx.x & 31;
    const int y = threadIdx.x >> 5;
    const int col = blockIdx.x * 32 + x;
    const int z = blockIdx.y;
    const float* Sbb = S + (long long)z * (LO * LDOC);
    const float* qlb = ql + (long long)z * LO;

    float vals[LO / 8];
    float m = -3.4e38f;
    #pragma unroll 4
    for (int it = 0; it < LO / 8; ++it) {
        const int r = it * 8 + y;
        float v = qlb[r] + Sbb[(long long)r * LDOC + col];
        vals[it] = v;
        m = fmaxf(m, v);
    }
    __shared__ float red[8][32];
    red[y][x] = m;
    __syncthreads();
    if (y == 0) {
        float mm = red[0][x];
        #pragma unroll
        for (int t = 1; t < 8; ++t) mm = fmaxf(mm, red[t][x]);
        red[0][x] = mm;
    }
    __syncthreads();
    m = red[0][x];
    __syncthreads();

    float s = 0.0f;
    #pragma unroll 4
    for (int it = 0; it < LO / 8; ++it) { vals[it] = expf(vals[it] - m); s += vals[it]; }
    red[y][x] = s;
    __syncthreads();
    if (y == 0) {
        float ss = 0.0f;
        #pragma unroll
        for (int t = 0; t < 8; ++t) ss += red[t][x];
        red[0][x] = ss;
    }
    __syncthreads();
    const float inv = 1.0f / red[0][x];

    __half* kqb = kq + (long long)z * (LO * LDOC);
    #pragma unroll 4
    for (int it = 0; it < LO / 8; ++it)
        kqb[(long long)(it * 8 + y) * LDOC + col] = __float2half(vals[it] * inv);
}

// ---------------- final max over positions ----------------
__global__ void maxreduce_kernel(const __half* __restrict__ f, float* __restrict__ out)
{
    const int h = blockIdx.x * 256 + threadIdx.x;
    const int b = blockIdx.y;
    float m = -3.4e38f;
    const __half* base = f + (long long)b * LO * HD + h;
    #pragma unroll 8
    for (int r = 0; r < LO; ++r) m = fmaxf(m, __half2float(base[(long long)r * HD]));
    out[(long long)b * HD + h] = m;
}

// ---------------- host ----------------
static ZOffs zzero() { ZOffs z; for (int i = 0; i < 12; ++i) z.o[i] = 0; return z; }

extern "C" void kernel_launch(void* const* d_in, const int* in_sizes, int n_in,
                              void* d_out, int out_size)
{
    cudaFuncSetAttribute(tgemm_kernel<0, 0>, cudaFuncAttributeMaxDynamicSharedMemorySize, NT_SMEM);
    cudaFuncSetAttribute(tgemm_kernel<0, 1>, cudaFuncAttributeMaxDynamicSharedMemorySize, NT_SMEM);
    cudaFuncSetAttribute(tgemm_kernel<1, 0>, cudaFuncAttributeMaxDynamicSharedMemorySize, NT_SMEM);
    cudaFuncSetAttribute(segk_kernel, cudaFuncAttributeMaxDynamicSharedMemorySize, NT_SMEM);
    cudaFuncSetAttribute(nngemm_kernel<0>, cudaFuncAttributeMaxDynamicSharedMemorySize, NN_SMEM);
    cudaFuncSetAttribute(nngemm_kernel<1>, cudaFuncAttributeMaxDynamicSharedMemorySize, NN_SMEM);
    cudaFuncSetAttribute(nngemm_kernel<2>, cudaFuncAttributeMaxDynamicSharedMemorySize, NN_SMEM);

    const float* last   = (const float*)d_in[4];
    const float* ow2    = (const float*)d_in[6];
    const float* ow3    = (const float*)d_in[7];
    const float* dw1    = (const float*)d_in[8];
    const float* dw2    = (const float*)d_in[9];
    const float* dw3    = (const float*)d_in[10];
    const float* sw2    = (const float*)d_in[12];
    const float* sw3    = (const float*)d_in[13];
    const float* comp_w = (const float*)d_in[14];
    const float* comp_b = (const float*)d_in[15];
    const float* gate_w = (const float*)d_in[16];
    const float* gate_b = (const float*)d_in[17];
    const float* attn_w = (const float*)d_in[18];
    const float* attn_b = (const float*)d_in[19];
    const float* self_w = (const float*)d_in[20];
    const float* self_b = (const float*)d_in[21];

    float *S_, *kl_, *ql_;
    __half *hlast, *hmul, *hsub, *hP, *hkq, *hcow, *hcorr, *hopt, *ha, *hco, *hfus, *hsa, *hfm, *hfs;
    __half *hcompw, *hgatew, *hattnw, *hselfw, *haff;
    cudaGetSymbolAddress((void**)&S_,  g_S);
    cudaGetSymbolAddress((void**)&kl_, g_kl);
    cudaGetSymbolAddress((void**)&ql_, g_ql);
    cudaGetSymbolAddress((void**)&hlast, h_last);
    cudaGetSymbolAddress((void**)&hmul,  h_mul);
    cudaGetSymbolAddress((void**)&hsub,  h_sub);
    cudaGetSymbolAddress((void**)&hP,    h_P);
    cudaGetSymbolAddress((void**)&hkq,   h_kq);
    cudaGetSymbolAddress((void**)&hcow,  h_cow);
    cudaGetSymbolAddress((void**)&hcorr, h_corr);
    cudaGetSymbolAddress((void**)&hopt,  h_opt);
    cudaGetSymbolAddress((void**)&ha,    h_a);
    cudaGetSymbolAddress((void**)&hco,   h_co);
    cudaGetSymbolAddress((void**)&hfus,  h_fus);
    cudaGetSymbolAddress((void**)&hsa,   h_sa);
    cudaGetSymbolAddress((void**)&hfm,   h_fm);
    cudaGetSymbolAddress((void**)&hfs,   h_fs);
    cudaGetSymbolAddress((void**)&hcompw, h_compw);
    cudaGetSymbolAddress((void**)&hgatew, h_gatew);
    cudaGetSymbolAddress((void**)&hattnw, h_attnw);
    cudaGetSymbolAddress((void**)&hselfw, h_selfw);
    cudaGetSymbolAddress((void**)&haff,   h_aff);

    const long long sSeq = (long long)SEQ * HD;
    const long long sQ   = 4LL * SEQ * HD;
    const long long LoH  = (long long)LO * HD;

    // ===== input conversions =====
    cvt_kernel<<<(NBAT * (long long)SEQ * HD) / 1024, 256>>>(last, hlast, (long long)NBAT * SEQ * HD);
    cvt_kernel<<<(7LL * HD * HD) / 1024, 256>>>(comp_w, hcompw, 7LL * HD * HD);
    cvt_kernel<<<(2LL * HD * HD) / 1024, 256>>>(gate_w, hgatew, 2LL * HD * HD);
    cvt_kernel<<<(3LL * HD * HD) / 1024, 256>>>(attn_w, hattnw, 3LL * HD * HD);
    cvt_kernel<<<(4LL * HD * HD) / 1024, 256>>>(self_w, hselfw, 4LL * HD * HD);
    cvt_kernel<<<1, 256>>>(ow3, haff + 0 * HD, HD);
    cvt_kernel<<<1, 256>>>(ow2, haff + 1 * HD, HD);
    cvt_kernel<<<1, 256>>>(sw3, haff + 2 * HD, HD);
    cvt_kernel<<<1, 256>>>(sw2, haff + 3 * HD, HD);

    long long curoff[NL], kvoff[12];
    for (int i = 0; i < NL; ++i) curoff[i] = ((long long)i * SEQ + LDOC) * HD;
    for (int i = 0, p = 0; i < NL; ++i)
        for (int j = 0; j < NL; ++j) {
            if (j == i) continue;
            kvoff[p] = ((long long)j * SEQ + LDOC) * HD;
            ++p;
        }

    // ===== Stage A: 12 pair attentions (kl folded into A-affine) =====
    {
        ZOffs kvo = zzero(), ao = zzero(), co = zzero();
        for (int p = 0; p < 12; ++p) {
            kvo.o[p] = kvoff[p];
            ao.o[p] = curoff[p / 3];
            co.o[p] = (long long)p * NBZ * LO * LO;
        }
        tgemm_kernel<0, 1><<<dim3(LO / BN, LO / BM, 96), 256, NT_SMEM>>>(
            HD, hlast, HD, sQ, ao, hlast, HD, sQ, kvo,
            S_, LO, (long long)LO * LO, co, NBZ, nullptr,
            haff + 0 * HD, haff + 1 * HD);

        softmax_row_kernel<<<dim3(LO, 96), 256>>>(S_, hP, LO, (long long)LO * LO,
                                                  nullptr, zzero(), 0, NBZ, LO);

        ZOffs ato = zzero(), xo = zzero();
        for (int p = 0; p < 12; ++p) { ato.o[p] = (long long)p * NBZ * LoH; xo.o[p] = curoff[p / 3]; }
        nngemm_kernel<1><<<dim3(HD / BN, LO / BM, 96), 256, NN_SMEM>>>(
            LO, hP, LO, (long long)LO * LO, co, hlast, HD, sQ, kvo,
            nullptr, HD, LoH, ato, NBZ,
            hlast, xo, sQ, hmul, hsub);
    }

    // ===== comp: segmented GEMM K=7168 =====
    {
        HSegArgs sga = {};
        sga.segs[0] = {hlast, (long long)LDOC * HD, (long long)SEQ * HD, sQ};
        for (int m = 0; m < 3; ++m) {
            sga.segs[1 + 2 * m] = {hmul, (long long)m * NBZ * LoH, 3LL * NBZ * LoH, LoH};
            sga.segs[2 + 2 * m] = {hsub, (long long)m * NBZ * LoH, 3LL * NBZ * LoH, LoH};
        }
        sga.nseg = 7;
        ZOffs co = zzero();
        for (int i = 0; i < NL; ++i) co.o[i] = (long long)i * LoH;
        segk_kernel<<<dim3(HD / BN, LO / BM, 32), 256, NT_SMEM>>>(
            7 * HD, sga, hcompw, 7 * HD,
            hcorr, HD, 4 * LoH, co, NBZ,
            comp_b, 2, nullptr, 0, nullptr, 0);
    }

    // ===== Stage B: gate + blend -> opt =====
    {
        HSegArgs sga = {};
        sga.segs[0] = {hlast, (long long)LDOC * HD, 0, sSeq};
        sga.segs[1] = {hcorr, 0, 0, LoH};
        sga.nseg = 2;
        segk_kernel<<<dim3(HD / BN, LO / BM, 32), 256, NT_SMEM>>>(
            2 * HD, sga, hgatew, 2 * HD,
            hopt, HD, LoH, zzero(), NBAT,
            gate_b, 4, hlast + (long long)LDOC * HD, sSeq, hcorr, LoH);
    }

    // ===== Stage C: doc attention =====
    {
        ZOffs z0o = zzero();
        rowdot_kernel<<<dim3(LO, NBAT), 256>>>(hopt, z0o, NBAT, LoH, HD, dw1, ql_, LO, HD);
        rowdot_kernel<<<dim3(LDOC, NBAT), 256>>>(hlast, z0o, NBAT, sSeq, HD, dw2, kl_, LDOC, HD);

        tgemm_kernel<0, 0><<<dim3(LDOC / BN, LO / BM, 32), 256, NT_SMEM>>>(
            HD, hopt, HD, LoH, zzero(), hlast, HD, sSeq, zzero(),
            S_, LDOC, (long long)LO * LDOC, zzero(), NBAT, dw3, nullptr, nullptr);

        softmax_col_kernel<<<dim3(LDOC / 32, NBAT), 256>>>(S_, hkq, ql_);
        softmax_row_kernel<<<dim3(LO, NBAT), 256>>>(S_, hP, LDOC, (long long)LO * LDOC,
                                                    kl_, zzero(), LDOC, NBAT, LDOC);

        nngemm_kernel<0><<<dim3(HD / BN, LO / BM, 32), 256, NN_SMEM>>>(
            LDOC, hP, LDOC, (long long)LO * LDOC, zzero(), hlast, HD, sSeq, zzero(),
            ha, HD, LoH, zzero(), NBAT,
            nullptr, zzero(), 0, nullptr, nullptr);

        tgemm_kernel<1, 0><<<dim3(LO / BN, LO / BM, 32), 256, NT_SMEM>>>(
            LDOC, hP, LDOC, (long long)LO * LDOC, zzero(), hkq, LDOC, (long long)LO * LDOC, zzero(),
            hcow, LO, (long long)LO * LO, zzero(), NBAT, nullptr, nullptr, nullptr);

        nngemm_kernel<0><<<dim3(HD / BN, LO / BM, 32), 256, NN_SMEM>>>(
            LO, hcow, LO, (long long)LO * LO, zzero(), hopt, HD, LoH, zzero(),
            hco, HD, LoH, zzero(), NBAT,
            nullptr, zzero(), 0, nullptr, nullptr);
    }

    // ===== Stage D: fusion =====
    {
        HSegArgs sga = {};
        sga.segs[0] = {hopt, 0, 0, LoH};
        sga.segs[1] = {ha,   0, 0, LoH};
        sga.segs[2] = {hco,  0, 0, LoH};
        sga.nseg = 3;
        segk_kernel<<<dim3(HD / BN, LO / BM, 32), 256, NT_SMEM>>>(
            3 * HD, sga, hattnw, 3 * HD,
            hfus, HD, LoH, zzero(), NBAT,
            attn_b, 1, nullptr, 0, nullptr, 0);
    }

    // ===== Stage E: self attention (kl folded into A-affine) =====
    {
        tgemm_kernel<0, 1><<<dim3(LO / BN, LO / BM, 32), 256, NT_SMEM>>>(
            HD, hfus, HD, LoH, zzero(), hfus, HD, LoH, zzero(),
            S_, LO, (long long)LO * LO, zzero(), NBAT, nullptr,
            haff + 2 * HD, haff + 3 * HD);

        softmax_row_kernel<<<dim3(LO, NBAT), 256>>>(S_, hP, LO, (long long)LO * LO,
                                                    nullptr, zzero(), 0, NBAT, LO);

        nngemm_kernel<2><<<dim3(HD / BN, LO / BM, 32), 256, NN_SMEM>>>(
            LO, hP, LO, (long long)LO * LO, zzero(), hfus, HD, LoH, zzero(),
            hsa, HD, LoH, zzero(), NBAT,
            hfus, zzero(), LoH, hfm, hfs);
    }

    // ===== Stage F: fusion2 =====
    {
        HSegArgs sga = {};
        sga.segs[0] = {hfus, 0, 0, LoH};
        sga.segs[1] = {hsa,  0, 0, LoH};
        sga.segs[2] = {hfm,  0, 0, LoH};
        sga.segs[3] = {hfs,  0, 0, LoH};
        sga.nseg = 4;
        segk_kernel<<<dim3(HD / BN, LO / BM, 32), 256, NT_SMEM>>>(
            4 * HD, sga, hselfw, 4 * HD,
            hcorr, HD, LoH, zzero(), NBAT,
            self_b, 1, nullptr, 0, nullptr, 0);
    }

    // ===== Stage G =====
    maxreduce_kernel<<<dim3(HD / 256, NBAT), 256>>>(hcorr, (float*)d_out);
}